// round 9
// baseline (speedup 1.0000x reference)
#include <cuda_runtime.h>
#include <cuda_fp16.h>
#include <math.h>
#include <stdint.h>

#define BB 2048      // batch
#define CC 50000     // classes
#define DD 128       // latent dim
#define CCP 50176    // padded classes = 196*256

#define TM 128
#define TN 256
#define GRID_X (CCP / TN)    // 196
#define GRID_Y (BB / TM)     // 16

static __device__ __constant__ float kCosM = 0.9950041652780258f;   // cos(0.1)
static __device__ __constant__ float kSinM = 0.09983341664682815f;  // sin(0.1)
static __device__ __constant__ float kEps  = 1e-7f;
#define L2E 1.4426950408889634f

// ---- scratch (device globals; no allocations allowed) ----
__device__ __align__(128) __half g_Xh[BB * DD];
__device__ __align__(128) __half g_Wh[(size_t)CCP * DD];
__device__ float g_S1[BB];    // sum exp(wf)
__device__ float g_S2[BB];    // sum exp(20*wf) (unmargined; corrected in k_loss)
__device__ float g_mlab[BB];  // 20 * margined cosine at label
__device__ float g_corr[BB];  // exp(20*margined) - exp(20*wf_label)
__device__ int   g_cnt[GRID_Y];  // per-row-block completion counters

// ---------------------------------------------------------------------------
#define LDSM4(R, addr) \
    asm volatile("ldmatrix.sync.aligned.m8n8.x4.shared.b16 {%0,%1,%2,%3}, [%4];" \
        : "=r"((R)[0]), "=r"((R)[1]), "=r"((R)[2]), "=r"((R)[3]) : "r"(addr))

// fp16-accumulate MMA: d,c are 2 regs of f16x2
#define MMA16816H(C, A, B) \
    asm volatile("mma.sync.aligned.m16n8k16.row.col.f16.f16.f16.f16 " \
        "{%0,%1}, {%2,%3,%4,%5}, {%6,%7}, {%0,%1};" \
        : "+r"((C)[0]), "+r"((C)[1]) \
        : "r"((A)[0]), "r"((A)[1]), "r"((A)[2]), "r"((A)[3]), \
          "r"((B)[0]), "r"((B)[1]))

__device__ __forceinline__ uint32_t smem_to_u32(const void* p) {
    uint32_t a;
    asm("{ .reg .u64 t; cvta.to.shared.u64 t, %1; cvt.u32.u64 %0, t; }" : "=r"(a) : "l"(p));
    return a;
}

__device__ __forceinline__ float ex2(float x) {
    float y;
    asm("ex2.approx.ftz.f32 %0, %1;" : "=f"(y) : "f"(x));
    return y;
}

__device__ __forceinline__ float pow20(float p) {
    float p2 = p * p, p4 = p2 * p2, p8 = p4 * p4, p16 = p8 * p8;
    return p16 * p4;
}

// ---------------------------------------------------------------------------
// one warp per row: fp32 normalize, convert to fp16 (+ zero row sums/counters)
__global__ void k_prep_x(const float* __restrict__ x) {
    if (blockIdx.x == 0 && threadIdx.x < GRID_Y) g_cnt[threadIdx.x] = 0;
    int gw = (blockIdx.x * blockDim.x + threadIdx.x) >> 5;
    int lane = threadIdx.x & 31;
    if (gw >= BB) return;
    float4 v = reinterpret_cast<const float4*>(x + (size_t)gw * DD)[lane];
    float s = v.x*v.x + v.y*v.y + v.z*v.z + v.w*v.w;
    #pragma unroll
    for (int o = 16; o; o >>= 1) s += __shfl_xor_sync(0xffffffffu, s, o);
    float inv = 1.0f / fmaxf(sqrtf(s), 1e-12f);
    __half2 h01 = __floats2half2_rn(v.x * inv, v.y * inv);
    __half2 h23 = __floats2half2_rn(v.z * inv, v.w * inv);
    reinterpret_cast<uint2*>(g_Xh + (size_t)gw * DD)[lane] =
        make_uint2(*reinterpret_cast<uint32_t*>(&h01), *reinterpret_cast<uint32_t*>(&h23));
    if (lane == 0) { g_S1[gw] = 0.0f; g_S2[gw] = 0.0f; }
}

__global__ void k_prep_w(const float* __restrict__ W) {
    int gw = (blockIdx.x * blockDim.x + threadIdx.x) >> 5;
    int lane = threadIdx.x & 31;
    if (gw >= CCP) return;
    if (gw >= CC) {
        reinterpret_cast<uint2*>(g_Wh + (size_t)gw * DD)[lane] = make_uint2(0, 0);
        return;
    }
    float4 v = reinterpret_cast<const float4*>(W + (size_t)gw * DD)[lane];
    float s = v.x*v.x + v.y*v.y + v.z*v.z + v.w*v.w;
    #pragma unroll
    for (int o = 16; o; o >>= 1) s += __shfl_xor_sync(0xffffffffu, s, o);
    float inv = 1.0f / fmaxf(sqrtf(s), 1e-12f);
    __half2 h01 = __floats2half2_rn(v.x * inv, v.y * inv);
    __half2 h23 = __floats2half2_rn(v.z * inv, v.w * inv);
    reinterpret_cast<uint2*>(g_Wh + (size_t)gw * DD)[lane] =
        make_uint2(*reinterpret_cast<uint32_t*>(&h01), *reinterpret_cast<uint32_t*>(&h23));
}

// per-row label margin correction (exact fp32 recompute of label column)
__global__ void k_label(const float* __restrict__ x, const float* __restrict__ W,
                        const float* __restrict__ b, const int* __restrict__ labels) {
    int gw = (blockIdx.x * blockDim.x + threadIdx.x) >> 5;
    int lane = threadIdx.x & 31;
    if (gw >= BB) return;
    int lab = labels[gw];
    float4 xv = reinterpret_cast<const float4*>(x + (size_t)gw * DD)[lane];
    float4 wv = reinterpret_cast<const float4*>(W + (size_t)lab * DD)[lane];
    float sxx = xv.x*xv.x + xv.y*xv.y + xv.z*xv.z + xv.w*xv.w;
    float sww = wv.x*wv.x + wv.y*wv.y + wv.z*wv.z + wv.w*wv.w;
    float sxw = xv.x*wv.x + xv.y*wv.y + xv.z*wv.z + xv.w*wv.w;
    #pragma unroll
    for (int o = 16; o; o >>= 1) {
        sxx += __shfl_xor_sync(0xffffffffu, sxx, o);
        sww += __shfl_xor_sync(0xffffffffu, sww, o);
        sxw += __shfl_xor_sync(0xffffffffu, sxw, o);
    }
    if (lane == 0) {
        float wf = sxw / (fmaxf(sqrtf(sxx), 1e-12f) * fmaxf(sqrtf(sww), 1e-12f)) + b[lab];
        float t = fminf(fmaxf(wf, -1.0f + kEps), 1.0f - kEps);
        float ctm = t * kCosM - sqrtf(fmaxf(1.0f - t * t, 0.0f)) * kSinM;
        g_mlab[gw] = 20.0f * ctm;
        g_corr[gw] = ex2(20.0f * ctm * L2E) - ex2(20.0f * wf * L2E);
    }
}

// ---------------------------------------------------------------------------
// Fused single-pass kernel. CTA 128x256, 256 threads, 8 warps (64x64 tiles).
// GEMM -> p (fp32) -> S1/S2 global accumulate -> semaphore (per row-block)
// -> scale retained p by 1/S1 -> store final fp32 predictions.
// ---------------------------------------------------------------------------
#define OFF_AH    0                    // A: 128 rows * 256B = 32 KB
#define OFF_BH    32768                // B: 256 rows * 256B = 64 KB
#define OFF_BIAS  98304                // 256 floats
#define OFF_S1    99328                // 128 floats (sums, then 1/S1)
#define OFF_S2    99840                // 128 floats
#define SMEM_BYTES 100352

__device__ __forceinline__ void load_tile(const __half* __restrict__ src,
                                          int rowBase, char* dst, int tid, int nrows) {
    int iters = nrows * 16 / 256;
    for (int it = 0; it < iters; it++) {
        int idx = tid + it * 256;
        int row = idx >> 4, ch = idx & 15;
        uint4 v = reinterpret_cast<const uint4*>(src + (size_t)(rowBase + row) * DD)[ch];
        int chs = ch ^ (row & 7);
        *reinterpret_cast<uint4*>(dst + row * 256 + chs * 16) = v;
    }
}

__device__ __forceinline__ void gemm_core(uint32_t sbase, int wid, int lane,
                                          uint32_t c[4][8][2]) {
    #pragma unroll
    for (int mf = 0; mf < 4; mf++)
        #pragma unroll
        for (int nf = 0; nf < 8; nf++) { c[mf][nf][0] = 0u; c[mf][nf][1] = 0u; }

    const int wm = (wid & 1) * 64;
    const int wn = (wid >> 1) * 64;
    const int g = lane >> 3;
    const int r = lane & 7;
    const uint32_t rowA  = (uint32_t)(wm + (g & 1) * 8 + r);
    const uint32_t rowBq = (uint32_t)(wn + (g >> 1) * 8 + r);

    #pragma unroll
    for (int ks = 0; ks < 8; ks++) {
        uint32_t a[4][4];
        #pragma unroll
        for (int mf = 0; mf < 4; mf++) {
            uint32_t row = rowA + mf * 16;
            uint32_t chs = (uint32_t)((2 * ks + (g >> 1)) ^ r);
            LDSM4(a[mf], sbase + OFF_AH + row * 256 + chs * 16);
        }
        uint32_t b[8][2];
        #pragma unroll
        for (int q = 0; q < 4; q++) {
            uint32_t row = rowBq + q * 16;
            uint32_t chs = (uint32_t)((2 * ks + (g & 1)) ^ r);
            uint32_t t4[4];
            LDSM4(t4, sbase + OFF_BH + row * 256 + chs * 16);
            b[2*q][0] = t4[0]; b[2*q][1] = t4[1];
            b[2*q+1][0] = t4[2]; b[2*q+1][1] = t4[3];
        }
        #pragma unroll
        for (int mf = 0; mf < 4; mf++)
            #pragma unroll
            for (int nf = 0; nf < 8; nf++)
                MMA16816H(c[mf][nf], a[mf], b[nf]);
    }
}

__global__ __launch_bounds__(256, 2) void k_fused(const float* __restrict__ bias,
                                                  float* __restrict__ out) {
    extern __shared__ char smem[];
    const uint32_t sbase = smem_to_u32(smem);
    const int tid = threadIdx.x, wid = tid >> 5, lane = tid & 31;
    const int rowBase = blockIdx.y * TM, colBase = blockIdx.x * TN;
    const int wm = (wid & 1) * 64;
    const int wn = (wid >> 1) * 64;

    load_tile(g_Xh, rowBase, smem + OFF_AH, tid, TM);
    load_tile(g_Wh, colBase, smem + OFF_BH, tid, TN);

    float* sBias = (float*)(smem + OFF_BIAS);
    float* sS1   = (float*)(smem + OFF_S1);
    float* sS2   = (float*)(smem + OFF_S2);
    if (tid < TN) {
        int cg = colBase + tid;
        sBias[tid] = (cg < CC) ? bias[cg] * L2E : -1e30f;
    }
    if (tid < TM) { sS1[tid] = 0.0f; sS2[tid] = 0.0f; }
    __syncthreads();

    uint32_t c[4][8][2];
    gemm_core(sbase, wid, lane, c);

    // ---- phase 1: p = exp(wf) in fp32; accumulate S1/S2; repack p into c as half2 ----
    const int qrow = lane >> 2, qcol = lane & 3;
    #pragma unroll
    for (int mf = 0; mf < 4; mf++) {
        float s1lo = 0.f, s1hi = 0.f, s2lo = 0.f, s2hi = 0.f;
        #pragma unroll
        for (int nf = 0; nf < 8; nf++) {
            const int lc = wn + nf * 8 + qcol * 2;
            const float b0 = sBias[lc], b1 = sBias[lc + 1];
            float2 f01 = __half22float2(*reinterpret_cast<__half2*>(&c[mf][nf][0]));
            float2 f23 = __half22float2(*reinterpret_cast<__half2*>(&c[mf][nf][1]));
            float p0 = ex2(fmaf(f01.x, L2E, b0));
            float p1 = ex2(fmaf(f01.y, L2E, b1));
            float p2 = ex2(fmaf(f23.x, L2E, b0));
            float p3 = ex2(fmaf(f23.y, L2E, b1));
            s1lo += p0 + p1;
            s2lo += pow20(p0) + pow20(p1);
            s1hi += p2 + p3;
            s2hi += pow20(p2) + pow20(p3);
            __half2 h0 = __floats2half2_rn(p0, p1);
            __half2 h1 = __floats2half2_rn(p2, p3);
            c[mf][nf][0] = *reinterpret_cast<uint32_t*>(&h0);
            c[mf][nf][1] = *reinterpret_cast<uint32_t*>(&h1);
        }
        #pragma unroll
        for (int o = 1; o <= 2; o <<= 1) {
            s1lo += __shfl_xor_sync(0xffffffffu, s1lo, o);
            s1hi += __shfl_xor_sync(0xffffffffu, s1hi, o);
            s2lo += __shfl_xor_sync(0xffffffffu, s2lo, o);
            s2hi += __shfl_xor_sync(0xffffffffu, s2hi, o);
        }
        if (qcol == 0) {
            int lr0 = wm + mf * 16 + qrow;
            atomicAdd(&sS1[lr0], s1lo);
            atomicAdd(&sS1[lr0 + 8], s1hi);
            atomicAdd(&sS2[lr0], s2lo);
            atomicAdd(&sS2[lr0 + 8], s2hi);
        }
    }
    __syncthreads();
    if (tid < TM) {
        atomicAdd(&g_S1[rowBase + tid], sS1[tid]);
        atomicAdd(&g_S2[rowBase + tid], sS2[tid]);
    }
    __threadfence();
    __syncthreads();
    if (tid == 0) atomicAdd(&g_cnt[blockIdx.y], 1);

    // ---- semaphore: wait until all column-blocks of this row-block are done ----
    if (tid == 0) {
        while (atomicOr(&g_cnt[blockIdx.y], 0) < GRID_X) {}
    }
    __syncthreads();
    __threadfence();

    float* sInv = (float*)(smem + OFF_S1);   // reuse
    if (tid < TM) sInv[tid] = 1.0f / __ldcg(&g_S1[rowBase + tid]);
    __syncthreads();

    // ---- phase 2: scale retained p by 1/S1, store final fp32 predictions ----
    const bool full = (colBase + TN <= CC);
    #pragma unroll
    for (int mf = 0; mf < 4; mf++) {
        const int lr0 = wm + mf * 16 + qrow;
        const int lr1 = lr0 + 8;
        const float i0 = sInv[lr0], i1 = sInv[lr1];
        const size_t rb0 = (size_t)(rowBase + lr0) * CC;
        const size_t rb1 = (size_t)(rowBase + lr1) * CC;
        #pragma unroll
        for (int nf = 0; nf < 8; nf++) {
            const int lc = wn + nf * 8 + qcol * 2;
            const int gc = colBase + lc;
            float2 f01 = __half22float2(*reinterpret_cast<__half2*>(&c[mf][nf][0]));
            float2 f23 = __half22float2(*reinterpret_cast<__half2*>(&c[mf][nf][1]));
            if (full || gc < CC) {
                *reinterpret_cast<float2*>(&out[rb0 + gc]) = make_float2(f01.x * i0, f01.y * i0);
                *reinterpret_cast<float2*>(&out[rb1 + gc]) = make_float2(f23.x * i1, f23.y * i1);
            }
        }
    }
}

// ---------------------------------------------------------------------------
__global__ void k_loss(float* __restrict__ out, int out_size) {
    __shared__ float red[256];
    float s = 0.0f;
    for (int b = threadIdx.x; b < BB; b += 256)
        s += logf(g_S2[b] + g_corr[b]) - g_mlab[b];
    red[threadIdx.x] = s;
    __syncthreads();
    for (int o = 128; o; o >>= 1) {
        if (threadIdx.x < o) red[threadIdx.x] += red[threadIdx.x + o];
        __syncthreads();
    }
    if (threadIdx.x == 0) {
        float loss = red[0] / (float)BB;
        out[(size_t)BB * CC] = loss;
        if (out_size - 1 != (long long)BB * CC) out[out_size - 1] = loss;
    }
}

// ---------------------------------------------------------------------------
extern "C" void kernel_launch(void* const* d_in, const int* in_sizes, int n_in,
                              void* d_out, int out_size) {
    const float* x      = (const float*)d_in[0];
    const float* W      = (const float*)d_in[1];
    const float* bias   = (const float*)d_in[2];
    const int*   labels = (const int*)  d_in[3];
    float* out = (float*)d_out;

    static bool attr_set = false;
    if (!attr_set) {
        cudaFuncSetAttribute(k_fused, cudaFuncAttributeMaxDynamicSharedMemorySize, SMEM_BYTES);
        attr_set = true;
    }

    k_prep_x<<<BB / 8, 256>>>(x);
    k_prep_w<<<CCP / 8, 256>>>(W);
    k_label<<<BB / 8, 256>>>(x, W, bias, labels);

    dim3 grid(GRID_X, GRID_Y);      // (196, 16); linear id = y*196+x
    k_fused<<<grid, 256, SMEM_BYTES>>>(bias, out);

    k_loss<<<1, 256>>>(out, out_size);
}

// round 12
// speedup vs baseline: 1.3333x; 1.3333x over previous
#include <cuda_runtime.h>
#include <cuda_fp16.h>
#include <math.h>
#include <stdint.h>

#define BB 2048      // batch
#define CC 50000     // classes
#define DD 128       // latent dim
#define CCP 50176    // padded classes = 196*256

#define TM 128
#define TN 256

static __device__ __constant__ float kCosM = 0.9950041652780258f;   // cos(0.1)
static __device__ __constant__ float kSinM = 0.09983341664682815f;  // sin(0.1)
static __device__ __constant__ float kEps  = 1e-7f;
#define L2E 1.4426950408889634f

// ---- scratch (device globals; no allocations allowed) ----
__device__ __align__(128) __half g_Xh[BB * DD];
__device__ __align__(128) __half g_Wh[(size_t)CCP * DD];
__device__ float g_S1[BB];    // sum exp(wf)
__device__ float g_S2[BB];    // sum exp(20*wf) (unmargined; corrected in k_loss)
__device__ float g_mlab[BB];  // 20 * margined cosine at label
__device__ float g_corr[BB];  // exp(20*margined) - exp(20*wf_label)

// ---------------------------------------------------------------------------
#define LDSM4(R, addr) \
    asm volatile("ldmatrix.sync.aligned.m8n8.x4.shared.b16 {%0,%1,%2,%3}, [%4];" \
        : "=r"((R)[0]), "=r"((R)[1]), "=r"((R)[2]), "=r"((R)[3]) : "r"(addr))

// fp16-accumulate MMA: d,c are 2 regs of f16x2
#define MMA16816H(C, A, B) \
    asm volatile("mma.sync.aligned.m16n8k16.row.col.f16.f16.f16.f16 " \
        "{%0,%1}, {%2,%3,%4,%5}, {%6,%7}, {%0,%1};" \
        : "+r"((C)[0]), "+r"((C)[1]) \
        : "r"((A)[0]), "r"((A)[1]), "r"((A)[2]), "r"((A)[3]), \
          "r"((B)[0]), "r"((B)[1]))

__device__ __forceinline__ uint32_t smem_to_u32(const void* p) {
    uint32_t a;
    asm("{ .reg .u64 t; cvta.to.shared.u64 t, %1; cvt.u32.u64 %0, t; }" : "=r"(a) : "l"(p));
    return a;
}

__device__ __forceinline__ float ex2(float x) {
    float y;
    asm("ex2.approx.ftz.f32 %0, %1;" : "=f"(y) : "f"(x));
    return y;
}

__device__ __forceinline__ float pow20(float p) {
    float p2 = p * p, p4 = p2 * p2, p8 = p4 * p4, p16 = p8 * p8;
    return p16 * p4;
}

// ---------------------------------------------------------------------------
// Merged prep: blocks [0,256) normalize X (+zero sums); [256,6528) normalize W;
// [6528,6784) exact fp32 label-margin terms. One warp per row everywhere.
#define PX_B 256
#define PW_B (CCP / 8)          // 6272
#define PL_B 256
__global__ void k_prep(const float* __restrict__ x, const float* __restrict__ W,
                       const float* __restrict__ b, const int* __restrict__ labels) {
    const int wid = threadIdx.x >> 5, lane = threadIdx.x & 31;
    const int bx = blockIdx.x;
    if (bx < PX_B) {
        int gw = bx * 8 + wid;
        float4 v = reinterpret_cast<const float4*>(x + (size_t)gw * DD)[lane];
        float s = v.x*v.x + v.y*v.y + v.z*v.z + v.w*v.w;
        #pragma unroll
        for (int o = 16; o; o >>= 1) s += __shfl_xor_sync(0xffffffffu, s, o);
        float inv = 1.0f / fmaxf(sqrtf(s), 1e-12f);
        __half2 h01 = __floats2half2_rn(v.x * inv, v.y * inv);
        __half2 h23 = __floats2half2_rn(v.z * inv, v.w * inv);
        reinterpret_cast<uint2*>(g_Xh + (size_t)gw * DD)[lane] =
            make_uint2(*reinterpret_cast<uint32_t*>(&h01), *reinterpret_cast<uint32_t*>(&h23));
        if (lane == 0) { g_S1[gw] = 0.0f; g_S2[gw] = 0.0f; }
    } else if (bx < PX_B + PW_B) {
        int gw = (bx - PX_B) * 8 + wid;
        if (gw >= CC) {
            reinterpret_cast<uint2*>(g_Wh + (size_t)gw * DD)[lane] = make_uint2(0, 0);
            return;
        }
        float4 v = reinterpret_cast<const float4*>(W + (size_t)gw * DD)[lane];
        float s = v.x*v.x + v.y*v.y + v.z*v.z + v.w*v.w;
        #pragma unroll
        for (int o = 16; o; o >>= 1) s += __shfl_xor_sync(0xffffffffu, s, o);
        float inv = 1.0f / fmaxf(sqrtf(s), 1e-12f);
        __half2 h01 = __floats2half2_rn(v.x * inv, v.y * inv);
        __half2 h23 = __floats2half2_rn(v.z * inv, v.w * inv);
        reinterpret_cast<uint2*>(g_Wh + (size_t)gw * DD)[lane] =
            make_uint2(*reinterpret_cast<uint32_t*>(&h01), *reinterpret_cast<uint32_t*>(&h23));
    } else {
        int gw = (bx - PX_B - PW_B) * 8 + wid;
        int lab = labels[gw];
        float4 xv = reinterpret_cast<const float4*>(x + (size_t)gw * DD)[lane];
        float4 wv = reinterpret_cast<const float4*>(W + (size_t)lab * DD)[lane];
        float sxx = xv.x*xv.x + xv.y*xv.y + xv.z*xv.z + xv.w*xv.w;
        float sww = wv.x*wv.x + wv.y*wv.y + wv.z*wv.z + wv.w*wv.w;
        float sxw = xv.x*wv.x + xv.y*wv.y + xv.z*wv.z + xv.w*wv.w;
        #pragma unroll
        for (int o = 16; o; o >>= 1) {
            sxx += __shfl_xor_sync(0xffffffffu, sxx, o);
            sww += __shfl_xor_sync(0xffffffffu, sww, o);
            sxw += __shfl_xor_sync(0xffffffffu, sxw, o);
        }
        if (lane == 0) {
            float wf = sxw / (fmaxf(sqrtf(sxx), 1e-12f) * fmaxf(sqrtf(sww), 1e-12f)) + b[lab];
            float t = fminf(fmaxf(wf, -1.0f + kEps), 1.0f - kEps);
            float ctm = t * kCosM - sqrtf(fmaxf(1.0f - t * t, 0.0f)) * kSinM;
            g_mlab[gw] = 20.0f * ctm;
            g_corr[gw] = ex2(20.0f * ctm * L2E) - ex2(20.0f * wf * L2E);
        }
    }
}

// ---------------------------------------------------------------------------
// fp16-acc HMMA core. CTA 128x256, 256 threads, 8 warps as 2(m) x 4(n),
// warp tile 64x64. K=128 resident. Smem rows 256B, chunk^=(row&7) swizzle.
// ---------------------------------------------------------------------------
#define OFF_AH    0                    // A: 128 rows * 256B = 32 KB
#define OFF_BH    32768                // B: 256 rows * 256B = 64 KB
#define OFF_BIAS  98304                // 256 floats: bias*log2e
#define OFF_B20   99328                // 256 floats: bias*20*log2e
#define OFF_S1    100352               // 128 floats
#define OFF_S2    100864               // 128 floats
#define SMEM_BYTES 101376

__device__ __forceinline__ void load_tile(const __half* __restrict__ src,
                                          int rowBase, char* dst, int tid, int nrows) {
    int iters = nrows * 16 / 256;
    for (int it = 0; it < iters; it++) {
        int idx = tid + it * 256;
        int row = idx >> 4, ch = idx & 15;
        uint4 v = reinterpret_cast<const uint4*>(src + (size_t)(rowBase + row) * DD)[ch];
        int chs = ch ^ (row & 7);
        *reinterpret_cast<uint4*>(dst + row * 256 + chs * 16) = v;
    }
}

__device__ __forceinline__ void gemm_core(uint32_t sbase, int wid, int lane,
                                          uint32_t c[4][8][2]) {
    #pragma unroll
    for (int mf = 0; mf < 4; mf++)
        #pragma unroll
        for (int nf = 0; nf < 8; nf++) { c[mf][nf][0] = 0u; c[mf][nf][1] = 0u; }

    const int wm = (wid & 1) * 64;
    const int wn = (wid >> 1) * 64;
    const int g = lane >> 3;
    const int r = lane & 7;
    const uint32_t rowA  = (uint32_t)(wm + (g & 1) * 8 + r);
    const uint32_t rowBq = (uint32_t)(wn + (g >> 1) * 8 + r);

    #pragma unroll
    for (int ks = 0; ks < 8; ks++) {
        uint32_t a[4][4];
        #pragma unroll
        for (int mf = 0; mf < 4; mf++) {
            uint32_t row = rowA + mf * 16;
            uint32_t chs = (uint32_t)((2 * ks + (g >> 1)) ^ r);
            LDSM4(a[mf], sbase + OFF_AH + row * 256 + chs * 16);
        }
        uint32_t b[8][2];
        #pragma unroll
        for (int q = 0; q < 4; q++) {
            uint32_t row = rowBq + q * 16;
            uint32_t chs = (uint32_t)((2 * ks + (g & 1)) ^ r);
            uint32_t t4[4];
            LDSM4(t4, sbase + OFF_BH + row * 256 + chs * 16);
            b[2*q][0] = t4[0]; b[2*q][1] = t4[1];
            b[2*q+1][0] = t4[2]; b[2*q+1][1] = t4[3];
        }
        #pragma unroll
        for (int mf = 0; mf < 4; mf++)
            #pragma unroll
            for (int nf = 0; nf < 8; nf++)
                MMA16816H(c[mf][nf], a[mf], b[nf]);
    }
}

// ---------------------------------------------------------------------------
// Pass A: GEMM -> row sums S1, S2. No big stores.
// s2 contributions alternate pow20(p) (fma pipe) and direct ex2(20t) (MUFU)
// to balance the two pipes.
__global__ __launch_bounds__(256, 2) void k_sums(const float* __restrict__ bias) {
    extern __shared__ char smem[];
    const uint32_t sbase = smem_to_u32(smem);
    const int tid = threadIdx.x, wid = tid >> 5, lane = tid & 31;
    const int rowBase = blockIdx.y * TM, colBase = blockIdx.x * TN;
    const int wm = (wid & 1) * 64;
    const int wn = (wid >> 1) * 64;

    load_tile(g_Xh, rowBase, smem + OFF_AH, tid, TM);
    load_tile(g_Wh, colBase, smem + OFF_BH, tid, TN);

    float* sBias = (float*)(smem + OFF_BIAS);
    float* sB20  = (float*)(smem + OFF_B20);
    float* sS1   = (float*)(smem + OFF_S1);
    float* sS2   = (float*)(smem + OFF_S2);
    if (tid < TN) {
        int cg = colBase + tid;
        float bv = (cg < CC) ? bias[cg] : 0.0f;
        sBias[tid] = (cg < CC) ? bv * L2E : -1e30f;
        sB20[tid]  = (cg < CC) ? bv * (20.0f * L2E) : -1e30f;
    }
    if (tid < TM) { sS1[tid] = 0.0f; sS2[tid] = 0.0f; }
    __syncthreads();

    uint32_t c[4][8][2];
    gemm_core(sbase, wid, lane, c);

    const int qrow = lane >> 2, qcol = lane & 3;
    #pragma unroll
    for (int mf = 0; mf < 4; mf++) {
        float s1lo = 0.f, s1hi = 0.f, s2lo = 0.f, s2hi = 0.f;
        #pragma unroll
        for (int nf = 0; nf < 8; nf++) {
            const int lc = wn + nf * 8 + qcol * 2;
            const float b0 = sBias[lc], b1 = sBias[lc + 1];
            const float b20 = sB20[lc + 1];
            float2 f01 = __half22float2(*reinterpret_cast<__half2*>(&c[mf][nf][0]));
            float2 f23 = __half22float2(*reinterpret_cast<__half2*>(&c[mf][nf][1]));
            float p0 = ex2(fmaf(f01.x, L2E, b0));
            float p1 = ex2(fmaf(f01.y, L2E, b1));
            float p2 = ex2(fmaf(f23.x, L2E, b0));
            float p3 = ex2(fmaf(f23.y, L2E, b1));
            s1lo += p0 + p1;
            s1hi += p2 + p3;
            // col lc -> pow20 (fma pipe); col lc+1 -> direct ex2(20t) (MUFU pipe)
            s2lo += pow20(p0) + ex2(fmaf(f01.y, 20.0f * L2E, b20));
            s2hi += pow20(p2) + ex2(fmaf(f23.y, 20.0f * L2E, b20));
        }
        #pragma unroll
        for (int o = 1; o <= 2; o <<= 1) {
            s1lo += __shfl_xor_sync(0xffffffffu, s1lo, o);
            s1hi += __shfl_xor_sync(0xffffffffu, s1hi, o);
            s2lo += __shfl_xor_sync(0xffffffffu, s2lo, o);
            s2hi += __shfl_xor_sync(0xffffffffu, s2hi, o);
        }
        if (qcol == 0) {
            int lr0 = wm + mf * 16 + qrow;
            atomicAdd(&sS1[lr0], s1lo);
            atomicAdd(&sS1[lr0 + 8], s1hi);
            atomicAdd(&sS2[lr0], s2lo);
            atomicAdd(&sS2[lr0 + 8], s2hi);
        }
    }
    __syncthreads();
    if (tid < TM) {
        atomicAdd(&g_S1[rowBase + tid], sS1[tid]);
        atomicAdd(&g_S2[rowBase + tid], sS2[tid]);
    }
}

// ---------------------------------------------------------------------------
// Pass B: recompute GEMM, write final normalized fp32 predictions directly.
__global__ __launch_bounds__(256, 2) void k_write(const float* __restrict__ bias,
                                                  float* __restrict__ out) {
    extern __shared__ char smem[];
    const uint32_t sbase = smem_to_u32(smem);
    const int tid = threadIdx.x, wid = tid >> 5, lane = tid & 31;
    const int rowBase = blockIdx.y * TM, colBase = blockIdx.x * TN;
    const int wm = (wid & 1) * 64;
    const int wn = (wid >> 1) * 64;

    load_tile(g_Xh, rowBase, smem + OFF_AH, tid, TM);
    load_tile(g_Wh, colBase, smem + OFF_BH, tid, TN);

    float* sBias = (float*)(smem + OFF_BIAS);
    float* sInv  = (float*)(smem + OFF_S1);
    if (tid < TN) {
        int cg = colBase + tid;
        sBias[tid] = (cg < CC) ? bias[cg] * L2E : -1e30f;
    }
    if (tid < TM) sInv[tid] = 1.0f / g_S1[rowBase + tid];
    __syncthreads();

    uint32_t c[4][8][2];
    gemm_core(sbase, wid, lane, c);

    const int qrow = lane >> 2, qcol = lane & 3;
    const bool full = (colBase + TN <= CC);
    #pragma unroll
    for (int mf = 0; mf < 4; mf++) {
        const int lr0 = wm + mf * 16 + qrow;
        const int lr1 = lr0 + 8;
        const float i0 = sInv[lr0], i1 = sInv[lr1];
        const size_t rb0 = (size_t)(rowBase + lr0) * CC;
        const size_t rb1 = (size_t)(rowBase + lr1) * CC;
        #pragma unroll
        for (int nf = 0; nf < 8; nf++) {
            const int lc = wn + nf * 8 + qcol * 2;
            const int gc = colBase + lc;
            const float b0 = sBias[lc], b1 = sBias[lc + 1];
            float2 f01 = __half22float2(*reinterpret_cast<__half2*>(&c[mf][nf][0]));
            float2 f23 = __half22float2(*reinterpret_cast<__half2*>(&c[mf][nf][1]));
            float p0 = ex2(fmaf(f01.x, L2E, b0)) * i0;
            float p1 = ex2(fmaf(f01.y, L2E, b1)) * i0;
            float p2 = ex2(fmaf(f23.x, L2E, b0)) * i1;
            float p3 = ex2(fmaf(f23.y, L2E, b1)) * i1;
            if (full || gc < CC) {
                __stcs(reinterpret_cast<float2*>(&out[rb0 + gc]), make_float2(p0, p1));
                __stcs(reinterpret_cast<float2*>(&out[rb1 + gc]), make_float2(p2, p3));
            }
        }
    }
}

// ---------------------------------------------------------------------------
__global__ void k_loss(float* __restrict__ out, int out_size) {
    __shared__ float red[256];
    float s = 0.0f;
    for (int b = threadIdx.x; b < BB; b += 256)
        s += logf(g_S2[b] + g_corr[b]) - g_mlab[b];
    red[threadIdx.x] = s;
    __syncthreads();
    for (int o = 128; o; o >>= 1) {
        if (threadIdx.x < o) red[threadIdx.x] += red[threadIdx.x + o];
        __syncthreads();
    }
    if (threadIdx.x == 0) {
        float loss = red[0] / (float)BB;
        out[(size_t)BB * CC] = loss;
        if (out_size - 1 != (long long)BB * CC) out[out_size - 1] = loss;
    }
}

// ---------------------------------------------------------------------------
extern "C" void kernel_launch(void* const* d_in, const int* in_sizes, int n_in,
                              void* d_out, int out_size) {
    const float* x      = (const float*)d_in[0];
    const float* W      = (const float*)d_in[1];
    const float* bias   = (const float*)d_in[2];
    const int*   labels = (const int*)  d_in[3];
    float* out = (float*)d_out;

    static bool attr_set = false;
    if (!attr_set) {
        cudaFuncSetAttribute(k_sums,  cudaFuncAttributeMaxDynamicSharedMemorySize, SMEM_BYTES);
        cudaFuncSetAttribute(k_write, cudaFuncAttributeMaxDynamicSharedMemorySize, SMEM_BYTES);
        attr_set = true;
    }

    k_prep<<<PX_B + PW_B + PL_B, 256>>>(x, W, bias, labels);

    dim3 grid(CCP / TN, BB / TM);      // (196, 16)
    k_sums<<<grid, 256, SMEM_BYTES>>>(bias);
    k_write<<<grid, 256, SMEM_BYTES>>>(bias, out);

    k_loss<<<1, 256>>>(out, out_size);
}